// round 12
// baseline (speedup 1.0000x reference)
#include <cuda_runtime.h>
#include <math.h>

#define TSTEPS 12
#define BATCH  1024
#define HID    256
#define NN     4096
#define DD     256
#define MALL   (TSTEPS*BATCH)   // 12288

// ---------------- scratch (static device globals; no allocation) ----------------
__device__ float g_coef[9*NN];                    // stencil coefficients of A (per column)
__device__ float g_Wp[DD*NN];                     // W' = W_gnn folded with A   (4 MB)
__device__ float g_t2[MALL*DD];                   // sigmoid(x @ W'^T + b_gnn)  (12 MB)
__device__ float g_t4[MALL*DD];                   // sigmoid(t2 @ W_lin^T)      (12 MB)
__device__ float g_xW[(size_t)MALL*3*HID];        // GRU input projection       (36 MB)
__device__ float g_hW[BATCH*3*HID];               // per-step recurrent proj    (3 MB)
__device__ float g_hs[MALL*HID];                  // GRU layer-0 outputs        (12 MB)
__device__ float g_h [BATCH*HID];                 // current hidden state       (1 MB)

__device__ __forceinline__ float sigm(float x) { return 1.0f / (1.0f + expf(-x)); }

// ---------------- stage 0: fold sparse A into W_gnn ----------------
// A's nonzeros all sit at row-col offsets {0,±1,±63,±64,±65}.
__global__ void extract_coef(const float* __restrict__ A)
{
    int n = blockIdx.x * blockDim.x + threadIdx.x;
    if (n >= NN) return;
    const int offs[9] = {0,-1,1,64,-64,63,65,-65,-63};
#pragma unroll
    for (int j = 0; j < 9; j++) {
        int m = n + offs[j];
        g_coef[j*NN + n] = (m >= 0 && m < NN) ? A[(size_t)m * NN + n] : 0.0f;
    }
}

// W'[d,n] = sum_off A[n+off, n] * W_gnn[d, n+off]
__global__ void build_wp(const float* __restrict__ Wg)
{
    int n = blockIdx.x * blockDim.x + threadIdx.x;   // 0..4095 (coalesced)
    int d = blockIdx.y;                              // 0..255
    if (n >= NN) return;
    const int offs[9] = {0,-1,1,64,-64,63,65,-65,-63};
    float s = 0.0f;
#pragma unroll
    for (int j = 0; j < 9; j++) {
        int m = n + offs[j];
        if (m >= 0 && m < NN)
            s = fmaf(g_coef[j*NN + n], Wg[(size_t)d * NN + m], s);
    }
    g_Wp[(size_t)d * NN + n] = s;
}

// ---------------- generic C = act(A[M,K] @ W[N,K]^T + bias) ----------------
// Classic smem-tiled SGEMM; both operands K-major; smem staged transposed so the
// inner loop does broadcast / conflict-free float4 LDS.
template<int BM, int BN, int BK, int TM, int TN, int ACT>
__global__ void gemm_kernel(const float* __restrict__ A,
                            const float* __restrict__ W,
                            const float* __restrict__ bias,
                            float* __restrict__ C,
                            int M, int N, int K)
{
    constexpr int TX = BN / TN;
    constexpr int TY = BM / TM;
    constexpr int NT = TX * TY;
    constexpr int KV = BK / 4;
    constexpr int LA = (BM * KV) / NT;
    constexpr int LB = (BN * KV) / NT;
    static_assert(LA >= 1 && LB >= 1, "loader mapping");

    __shared__ float As[BK][BM];
    __shared__ float Ws[BK][BN];

    const int tid   = threadIdx.x;
    const int tx    = tid % TX;
    const int ty    = tid / TX;
    const int mBase = blockIdx.y * BM;
    const int nBase = blockIdx.x * BN;

    float acc[TM][TN];
#pragma unroll
    for (int i = 0; i < TM; i++)
#pragma unroll
        for (int j = 0; j < TN; j++) acc[i][j] = 0.0f;

    for (int k0 = 0; k0 < K; k0 += BK) {
#pragma unroll
        for (int i = 0; i < LA; i++) {
            int idx = tid + i * NT;
            int r = idx / KV, c = idx % KV;
            float4 v = *reinterpret_cast<const float4*>(A + (size_t)(mBase + r) * K + k0 + c * 4);
            As[c*4+0][r] = v.x; As[c*4+1][r] = v.y; As[c*4+2][r] = v.z; As[c*4+3][r] = v.w;
        }
#pragma unroll
        for (int i = 0; i < LB; i++) {
            int idx = tid + i * NT;
            int r = idx / KV, c = idx % KV;
            float4 v = *reinterpret_cast<const float4*>(W + (size_t)(nBase + r) * K + k0 + c * 4);
            Ws[c*4+0][r] = v.x; Ws[c*4+1][r] = v.y; Ws[c*4+2][r] = v.z; Ws[c*4+3][r] = v.w;
        }
        __syncthreads();

#pragma unroll
        for (int kk = 0; kk < BK; kk++) {
            float a[TM], b[TN];
#pragma unroll
            for (int i = 0; i < TM; i++) a[i] = As[kk][ty * TM + i];
#pragma unroll
            for (int j = 0; j < TN; j++) b[j] = Ws[kk][tx * TN + j];
#pragma unroll
            for (int i = 0; i < TM; i++)
#pragma unroll
                for (int j = 0; j < TN; j++)
                    acc[i][j] = fmaf(a[i], b[j], acc[i][j]);
        }
        __syncthreads();
    }

#pragma unroll
    for (int i = 0; i < TM; i++) {
        int m = mBase + ty * TM + i;
#pragma unroll
        for (int j0 = 0; j0 < TN; j0 += 4) {
            int n = nBase + tx * TN + j0;
            float v0 = acc[i][j0+0] + bias[n+0];
            float v1 = acc[i][j0+1] + bias[n+1];
            float v2 = acc[i][j0+2] + bias[n+2];
            float v3 = acc[i][j0+3] + bias[n+3];
            if (ACT) { v0 = sigm(v0); v1 = sigm(v1); v2 = sigm(v2); v3 = sigm(v3); }
            float4 o; o.x = v0; o.y = v1; o.z = v2; o.w = v3;
            *reinterpret_cast<float4*>(C + (size_t)m * N + n) = o;
        }
    }
}

// ---------------- GRU pieces ----------------
__global__ void set_h(const float* __restrict__ src)
{
    int i = blockIdx.x * blockDim.x + threadIdx.x;
    g_h[i] = src[i];
}

// PyTorch GRU cell gate math (gate order r, z, n). In-place h update.
__global__ void gru_gate(const float* __restrict__ xW,
                         const float* __restrict__ hW,
                         float* __restrict__ h,
                         float* __restrict__ hs_out)
{
    int idx = blockIdx.x * blockDim.x + threadIdx.x;   // b*HID + j
    int b = idx / HID, j = idx % HID;
    size_t base = (size_t)b * 3 * HID;
    float r = sigm(xW[base + j]         + hW[base + j]);
    float z = sigm(xW[base + HID + j]   + hW[base + HID + j]);
    float n = tanhf(xW[base + 2*HID + j] + r * hW[base + 2*HID + j]);
    float hp = h[idx];
    float hn = (1.0f - z) * n + z * hp;
    h[idx] = hn;
    if (hs_out) hs_out[idx] = hn;
}

// ---------------- final 3-layer sigmoid MLP on last hidden state ----------------
__global__ void final_mlp(const float* __restrict__ h,
                          const float* __restrict__ Wf0, const float* __restrict__ bf0,
                          const float* __restrict__ Wf1, const float* __restrict__ bf1,
                          const float* __restrict__ Wf2, const float* __restrict__ bf2,
                          float* __restrict__ out)
{
    __shared__ float sW0[16][257];   // padded vs bank conflicts
    __shared__ float sh [16][256];
    __shared__ float s1 [16][17];
    __shared__ float s2 [16][17];

    int tid = threadIdx.x;           // 256 threads: 16 rows x 16 cols
    int bb  = blockIdx.x * 16;

    for (int i = tid; i < 16 * 256; i += 256) sW0[i / 256][i % 256] = Wf0[i];
    for (int i = tid; i < 16 * 256; i += 256) sh [i / 256][i % 256] = h[(size_t)bb * 256 + i];
    __syncthreads();

    int r = tid / 16, j = tid % 16;
    float a0 = bf0[j];
#pragma unroll 8
    for (int k = 0; k < 256; k++) a0 = fmaf(sh[r][k], sW0[j][k], a0);
    s1[r][j] = sigm(a0);
    __syncthreads();

    float a1 = bf1[j];
#pragma unroll
    for (int k = 0; k < 16; k++) a1 = fmaf(s1[r][k], Wf1[j * 16 + k], a1);
    s2[r][j] = sigm(a1);
    __syncthreads();

    if (j == 0) {
        float a2 = bf2[0];
#pragma unroll
        for (int k = 0; k < 16; k++) a2 = fmaf(s2[r][k], Wf2[k], a2);
        out[bb + r] = sigm(a2);
    }
}

// ---------------- launch ----------------
extern "C" void kernel_launch(void* const* d_in, const int* in_sizes, int n_in,
                              void* d_out, int out_size)
{
    const float* x     = (const float*)d_in[0];
    const float* h0    = (const float*)d_in[1];
    const float* Aadj  = (const float*)d_in[2];
    const float* W_gnn = (const float*)d_in[3];
    const float* b_gnn = (const float*)d_in[4];
    const float* W_lin = (const float*)d_in[5];
    const float* b_lin = (const float*)d_in[6];
    const float* Wih0  = (const float*)d_in[7];
    const float* Whh0  = (const float*)d_in[8];
    const float* bih0  = (const float*)d_in[9];
    const float* bhh0  = (const float*)d_in[10];
    const float* Wih1  = (const float*)d_in[11];
    const float* Whh1  = (const float*)d_in[12];
    const float* bih1  = (const float*)d_in[13];
    const float* bhh1  = (const float*)d_in[14];
    const float* Wf0   = (const float*)d_in[15];
    const float* bf0   = (const float*)d_in[16];
    const float* Wf1   = (const float*)d_in[17];
    const float* bf1   = (const float*)d_in[18];
    const float* Wf2   = (const float*)d_in[19];
    const float* bf2   = (const float*)d_in[20];
    float* out = (float*)d_out;

    float *p_Wp, *p_t2, *p_t4, *p_xW, *p_hW, *p_hs, *p_h;
    cudaGetSymbolAddress((void**)&p_Wp, g_Wp);
    cudaGetSymbolAddress((void**)&p_t2, g_t2);
    cudaGetSymbolAddress((void**)&p_t4, g_t4);
    cudaGetSymbolAddress((void**)&p_xW, g_xW);
    cudaGetSymbolAddress((void**)&p_hW, g_hW);
    cudaGetSymbolAddress((void**)&p_hs, g_hs);
    cudaGetSymbolAddress((void**)&p_h,  g_h);

    // 0) fold A into W_gnn  (W' = W_gnn . A restricted to the 9-offset stencil)
    extract_coef<<<NN / 256, 256>>>(Aadj);
    build_wp<<<dim3(NN / 256, DD), 256>>>(W_gnn);

    // 1) t2 = sigmoid(x @ W'^T + b_gnn)        [12288, 4096] x [4096, 256]
    gemm_kernel<128, 64, 16, 8, 4, 1>
        <<<dim3(DD / 64, MALL / 128), 256>>>(x, p_Wp, b_gnn, p_t2, MALL, DD, NN);

    // 2) t4 = sigmoid(t2 @ W_lin^T + b_lin)    [12288, 256] x [256, 256]
    gemm_kernel<128, 64, 16, 8, 4, 1>
        <<<dim3(DD / 64, MALL / 128), 256>>>(p_t2, W_lin, b_lin, p_t4, MALL, DD, DD);

    // 3) GRU layer 0
    gemm_kernel<128, 64, 16, 8, 4, 0>
        <<<dim3(3 * HID / 64, MALL / 128), 256>>>(p_t4, Wih0, bih0, p_xW, MALL, 3 * HID, DD);
    set_h<<<BATCH * HID / 256, 256>>>(h0);
    for (int t = 0; t < TSTEPS; t++) {
        gemm_kernel<64, 64, 16, 4, 4, 0>
            <<<dim3(3 * HID / 64, BATCH / 64), 256>>>(p_h, Whh0, bhh0, p_hW, BATCH, 3 * HID, HID);
        gru_gate<<<BATCH * HID / 256, 256>>>(p_xW + (size_t)t * BATCH * 3 * HID, p_hW,
                                             p_h, p_hs + (size_t)t * BATCH * HID);
    }

    // 4) GRU layer 1 (input = layer-0 hidden sequence)
    gemm_kernel<128, 64, 16, 8, 4, 0>
        <<<dim3(3 * HID / 64, MALL / 128), 256>>>(p_hs, Wih1, bih1, p_xW, MALL, 3 * HID, HID);
    set_h<<<BATCH * HID / 256, 256>>>(h0 + BATCH * HID);
    for (int t = 0; t < TSTEPS; t++) {
        gemm_kernel<64, 64, 16, 4, 4, 0>
            <<<dim3(3 * HID / 64, BATCH / 64), 256>>>(p_h, Whh1, bhh1, p_hW, BATCH, 3 * HID, HID);
        gru_gate<<<BATCH * HID / 256, 256>>>(p_xW + (size_t)t * BATCH * 3 * HID, p_hW,
                                             p_h, nullptr);
    }

    // 5) final MLP -> out [1024]
    final_mlp<<<BATCH / 16, 256>>>(p_h, Wf0, bf0, Wf1, bf1, Wf2, bf2, out);
}

// round 13
// speedup vs baseline: 1.0040x; 1.0040x over previous
#include <cuda_runtime.h>
#include <math.h>

#define TSTEPS 12
#define BATCH  1024
#define HID    256
#define NN     4096
#define DD     256
#define MALL   (TSTEPS*BATCH)   // 12288

// ---------------- scratch (static device globals; no allocation) ----------------
__device__ float g_coef[9*NN];                    // stencil coefficients of A (per column)
__device__ float g_Wp[DD*NN];                     // W' = W_gnn folded with A   (4 MB)
__device__ float g_t2[MALL*DD];                   // sigmoid(x @ W'^T + b_gnn)  (12 MB)
__device__ float g_t4[MALL*DD];                   // sigmoid(t2 @ W_lin^T)      (12 MB)
__device__ float g_xW[(size_t)MALL*3*HID];        // GRU input projection       (36 MB)
__device__ float g_hW[BATCH*3*HID];               // per-step recurrent proj    (3 MB)
__device__ float g_hs[MALL*HID];                  // GRU layer-0 outputs        (12 MB)
__device__ float g_h [BATCH*HID];                 // current hidden state       (1 MB)

__device__ __forceinline__ float sigm(float x) { return 1.0f / (1.0f + expf(-x)); }

// ---------------- stage 0: fold sparse A into W_gnn ----------------
// A's nonzeros all sit at row-col offsets {0,±1,±63,±64,±65}.
__global__ void extract_coef(const float* __restrict__ A)
{
    int n = blockIdx.x * blockDim.x + threadIdx.x;
    if (n >= NN) return;
    const int offs[9] = {0,-1,1,64,-64,63,65,-65,-63};
#pragma unroll
    for (int j = 0; j < 9; j++) {
        int m = n + offs[j];
        g_coef[j*NN + n] = (m >= 0 && m < NN) ? A[(size_t)m * NN + n] : 0.0f;
    }
}

// W'[d,n] = sum_off A[n+off, n] * W_gnn[d, n+off]
__global__ void build_wp(const float* __restrict__ Wg)
{
    int n = blockIdx.x * blockDim.x + threadIdx.x;   // 0..4095 (coalesced)
    int d = blockIdx.y;                              // 0..255
    if (n >= NN) return;
    const int offs[9] = {0,-1,1,64,-64,63,65,-65,-63};
    float s = 0.0f;
#pragma unroll
    for (int j = 0; j < 9; j++) {
        int m = n + offs[j];
        if (m >= 0 && m < NN)
            s = fmaf(g_coef[j*NN + n], Wg[(size_t)d * NN + m], s);
    }
    g_Wp[(size_t)d * NN + n] = s;
}

// ---------------- generic C = act(A[M,K] @ W[N,K]^T + bias) ----------------
// Classic smem-tiled SGEMM; both operands K-major; smem staged transposed so the
// inner loop does broadcast / conflict-free float4 LDS.
template<int BM, int BN, int BK, int TM, int TN, int ACT>
__global__ void gemm_kernel(const float* __restrict__ A,
                            const float* __restrict__ W,
                            const float* __restrict__ bias,
                            float* __restrict__ C,
                            int M, int N, int K)
{
    constexpr int TX = BN / TN;
    constexpr int TY = BM / TM;
    constexpr int NT = TX * TY;
    constexpr int KV = BK / 4;
    constexpr int LA = (BM * KV) / NT;
    constexpr int LB = (BN * KV) / NT;
    static_assert(LA >= 1 && LB >= 1, "loader mapping");

    __shared__ float As[BK][BM];
    __shared__ float Ws[BK][BN];

    const int tid   = threadIdx.x;
    const int tx    = tid % TX;
    const int ty    = tid / TX;
    const int mBase = blockIdx.y * BM;
    const int nBase = blockIdx.x * BN;

    float acc[TM][TN];
#pragma unroll
    for (int i = 0; i < TM; i++)
#pragma unroll
        for (int j = 0; j < TN; j++) acc[i][j] = 0.0f;

    for (int k0 = 0; k0 < K; k0 += BK) {
#pragma unroll
        for (int i = 0; i < LA; i++) {
            int idx = tid + i * NT;
            int r = idx / KV, c = idx % KV;
            float4 v = *reinterpret_cast<const float4*>(A + (size_t)(mBase + r) * K + k0 + c * 4);
            As[c*4+0][r] = v.x; As[c*4+1][r] = v.y; As[c*4+2][r] = v.z; As[c*4+3][r] = v.w;
        }
#pragma unroll
        for (int i = 0; i < LB; i++) {
            int idx = tid + i * NT;
            int r = idx / KV, c = idx % KV;
            float4 v = *reinterpret_cast<const float4*>(W + (size_t)(nBase + r) * K + k0 + c * 4);
            Ws[c*4+0][r] = v.x; Ws[c*4+1][r] = v.y; Ws[c*4+2][r] = v.z; Ws[c*4+3][r] = v.w;
        }
        __syncthreads();

#pragma unroll
        for (int kk = 0; kk < BK; kk++) {
            float a[TM], b[TN];
#pragma unroll
            for (int i = 0; i < TM; i++) a[i] = As[kk][ty * TM + i];
#pragma unroll
            for (int j = 0; j < TN; j++) b[j] = Ws[kk][tx * TN + j];
#pragma unroll
            for (int i = 0; i < TM; i++)
#pragma unroll
                for (int j = 0; j < TN; j++)
                    acc[i][j] = fmaf(a[i], b[j], acc[i][j]);
        }
        __syncthreads();
    }

#pragma unroll
    for (int i = 0; i < TM; i++) {
        int m = mBase + ty * TM + i;
#pragma unroll
        for (int j0 = 0; j0 < TN; j0 += 4) {
            int n = nBase + tx * TN + j0;
            float v0 = acc[i][j0+0] + bias[n+0];
            float v1 = acc[i][j0+1] + bias[n+1];
            float v2 = acc[i][j0+2] + bias[n+2];
            float v3 = acc[i][j0+3] + bias[n+3];
            if (ACT) { v0 = sigm(v0); v1 = sigm(v1); v2 = sigm(v2); v3 = sigm(v3); }
            float4 o; o.x = v0; o.y = v1; o.z = v2; o.w = v3;
            *reinterpret_cast<float4*>(C + (size_t)m * N + n) = o;
        }
    }
}

// ---------------- GRU pieces ----------------
__global__ void set_h(const float* __restrict__ src)
{
    int i = blockIdx.x * blockDim.x + threadIdx.x;
    g_h[i] = src[i];
}

// PyTorch GRU cell gate math (gate order r, z, n). In-place h update.
__global__ void gru_gate(const float* __restrict__ xW,
                         const float* __restrict__ hW,
                         float* __restrict__ h,
                         float* __restrict__ hs_out)
{
    int idx = blockIdx.x * blockDim.x + threadIdx.x;   // b*HID + j
    int b = idx / HID, j = idx % HID;
    size_t base = (size_t)b * 3 * HID;
    float r = sigm(xW[base + j]         + hW[base + j]);
    float z = sigm(xW[base + HID + j]   + hW[base + HID + j]);
    float n = tanhf(xW[base + 2*HID + j] + r * hW[base + 2*HID + j]);
    float hp = h[idx];
    float hn = (1.0f - z) * n + z * hp;
    h[idx] = hn;
    if (hs_out) hs_out[idx] = hn;
}

// ---------------- final 3-layer sigmoid MLP on last hidden state ----------------
__global__ void final_mlp(const float* __restrict__ h,
                          const float* __restrict__ Wf0, const float* __restrict__ bf0,
                          const float* __restrict__ Wf1, const float* __restrict__ bf1,
                          const float* __restrict__ Wf2, const float* __restrict__ bf2,
                          float* __restrict__ out)
{
    __shared__ float sW0[16][257];   // padded vs bank conflicts
    __shared__ float sh [16][256];
    __shared__ float s1 [16][17];
    __shared__ float s2 [16][17];

    int tid = threadIdx.x;           // 256 threads: 16 rows x 16 cols
    int bb  = blockIdx.x * 16;

    for (int i = tid; i < 16 * 256; i += 256) sW0[i / 256][i % 256] = Wf0[i];
    for (int i = tid; i < 16 * 256; i += 256) sh [i / 256][i % 256] = h[(size_t)bb * 256 + i];
    __syncthreads();

    int r = tid / 16, j = tid % 16;
    float a0 = bf0[j];
#pragma unroll 8
    for (int k = 0; k < 256; k++) a0 = fmaf(sh[r][k], sW0[j][k], a0);
    s1[r][j] = sigm(a0);
    __syncthreads();

    float a1 = bf1[j];
#pragma unroll
    for (int k = 0; k < 16; k++) a1 = fmaf(s1[r][k], Wf1[j * 16 + k], a1);
    s2[r][j] = sigm(a1);
    __syncthreads();

    if (j == 0) {
        float a2 = bf2[0];
#pragma unroll
        for (int k = 0; k < 16; k++) a2 = fmaf(s2[r][k], Wf2[k], a2);
        out[bb + r] = sigm(a2);
    }
}

// ---------------- launch ----------------
extern "C" void kernel_launch(void* const* d_in, const int* in_sizes, int n_in,
                              void* d_out, int out_size)
{
    const float* x     = (const float*)d_in[0];
    const float* h0    = (const float*)d_in[1];
    const float* Aadj  = (const float*)d_in[2];
    const float* W_gnn = (const float*)d_in[3];
    const float* b_gnn = (const float*)d_in[4];
    const float* W_lin = (const float*)d_in[5];
    const float* b_lin = (const float*)d_in[6];
    const float* Wih0  = (const float*)d_in[7];
    const float* Whh0  = (const float*)d_in[8];
    const float* bih0  = (const float*)d_in[9];
    const float* bhh0  = (const float*)d_in[10];
    const float* Wih1  = (const float*)d_in[11];
    const float* Whh1  = (const float*)d_in[12];
    const float* bih1  = (const float*)d_in[13];
    const float* bhh1  = (const float*)d_in[14];
    const float* Wf0   = (const float*)d_in[15];
    const float* bf0   = (const float*)d_in[16];
    const float* Wf1   = (const float*)d_in[17];
    const float* bf1   = (const float*)d_in[18];
    const float* Wf2   = (const float*)d_in[19];
    const float* bf2   = (const float*)d_in[20];
    float* out = (float*)d_out;

    float *p_Wp, *p_t2, *p_t4, *p_xW, *p_hW, *p_hs, *p_h;
    cudaGetSymbolAddress((void**)&p_Wp, g_Wp);
    cudaGetSymbolAddress((void**)&p_t2, g_t2);
    cudaGetSymbolAddress((void**)&p_t4, g_t4);
    cudaGetSymbolAddress((void**)&p_xW, g_xW);
    cudaGetSymbolAddress((void**)&p_hW, g_hW);
    cudaGetSymbolAddress((void**)&p_hs, g_hs);
    cudaGetSymbolAddress((void**)&p_h,  g_h);

    // 0) fold A into W_gnn  (W' = W_gnn . A restricted to the 9-offset stencil)
    extract_coef<<<NN / 256, 256>>>(Aadj);
    build_wp<<<dim3(NN / 256, DD), 256>>>(W_gnn);

    // 1) t2 = sigmoid(x @ W'^T + b_gnn)        [12288, 4096] x [4096, 256]
    gemm_kernel<128, 64, 16, 8, 4, 1>
        <<<dim3(DD / 64, MALL / 128), 256>>>(x, p_Wp, b_gnn, p_t2, MALL, DD, NN);

    // 2) t4 = sigmoid(t2 @ W_lin^T + b_lin)    [12288, 256] x [256, 256]
    gemm_kernel<128, 64, 16, 8, 4, 1>
        <<<dim3(DD / 64, MALL / 128), 256>>>(p_t2, W_lin, b_lin, p_t4, MALL, DD, DD);

    // 3) GRU layer 0
    gemm_kernel<128, 64, 16, 8, 4, 0>
        <<<dim3(3 * HID / 64, MALL / 128), 256>>>(p_t4, Wih0, bih0, p_xW, MALL, 3 * HID, DD);
    set_h<<<BATCH * HID / 256, 256>>>(h0);
    for (int t = 0; t < TSTEPS; t++) {
        gemm_kernel<64, 64, 16, 4, 4, 0>
            <<<dim3(3 * HID / 64, BATCH / 64), 256>>>(p_h, Whh0, bhh0, p_hW, BATCH, 3 * HID, HID);
        gru_gate<<<BATCH * HID / 256, 256>>>(p_xW + (size_t)t * BATCH * 3 * HID, p_hW,
                                             p_h, p_hs + (size_t)t * BATCH * HID);
    }

    // 4) GRU layer 1 (input = layer-0 hidden sequence)
    gemm_kernel<128, 64, 16, 8, 4, 0>
        <<<dim3(3 * HID / 64, MALL / 128), 256>>>(p_hs, Wih1, bih1, p_xW, MALL, 3 * HID, HID);
    set_h<<<BATCH * HID / 256, 256>>>(h0 + BATCH * HID);
    for (int t = 0; t < TSTEPS; t++) {
        gemm_kernel<64, 64, 16, 4, 4, 0>
            <<<dim3(3 * HID / 64, BATCH / 64), 256>>>(p_h, Whh1, bhh1, p_hW, BATCH, 3 * HID, HID);
        gru_gate<<<BATCH * HID / 256, 256>>>(p_xW + (size_t)t * BATCH * 3 * HID, p_hW,
                                             p_h, nullptr);
    }

    // 5) final MLP -> out [1024]
    final_mlp<<<BATCH / 16, 256>>>(p_h, Wf0, bf0, Wf1, bf1, Wf2, bf2, out);
}

// round 14
// speedup vs baseline: 2.3986x; 2.3889x over previous
#include <cuda_runtime.h>
#include <math.h>

#define TSTEPS 12
#define BATCH  1024
#define HID    256
#define NN     4096
#define DD     256
#define MALL   (TSTEPS*BATCH)   // 12288

// ---------------- scratch (static device globals; no allocation) ----------------
__device__ float g_coef[9*NN];
__device__ float g_Wp[DD*NN];
__device__ float g_t2[MALL*DD];
__device__ float g_t4[MALL*DD];
__device__ float g_xW[(size_t)MALL*3*HID];
__device__ float g_hW[BATCH*3*HID];
__device__ float g_hs[MALL*HID];
__device__ float g_h [BATCH*HID];

__device__ __forceinline__ float sigm(float x) { return 1.0f / (1.0f + expf(-x)); }

__device__ __forceinline__ unsigned f2tf(float f) {
    unsigned u;
    asm("cvt.rna.tf32.f32 %0, %1;" : "=r"(u) : "f"(f));
    return u;
}

__device__ __forceinline__ void mma_tf32(float* c, const unsigned* a, const unsigned* b) {
    asm volatile(
        "mma.sync.aligned.m16n8k8.row.col.f32.tf32.tf32.f32 "
        "{%0,%1,%2,%3}, {%4,%5,%6,%7}, {%8,%9}, {%0,%1,%2,%3};"
        : "+f"(c[0]), "+f"(c[1]), "+f"(c[2]), "+f"(c[3])
        : "r"(a[0]), "r"(a[1]), "r"(a[2]), "r"(a[3]), "r"(b[0]), "r"(b[1]));
}

// ---------------- stage 0: fold sparse A into W_gnn ----------------
__global__ void extract_coef(const float* __restrict__ A)
{
    int n = blockIdx.x * blockDim.x + threadIdx.x;
    if (n >= NN) return;
    const int offs[9] = {0,-1,1,64,-64,63,65,-65,-63};
#pragma unroll
    for (int j = 0; j < 9; j++) {
        int m = n + offs[j];
        g_coef[j*NN + n] = (m >= 0 && m < NN) ? A[(size_t)m * NN + n] : 0.0f;
    }
}

__global__ void build_wp(const float* __restrict__ Wg)
{
    int n = blockIdx.x * blockDim.x + threadIdx.x;
    int d = blockIdx.y;
    if (n >= NN) return;
    const int offs[9] = {0,-1,1,64,-64,63,65,-65,-63};
    float s = 0.0f;
#pragma unroll
    for (int j = 0; j < 9; j++) {
        int m = n + offs[j];
        if (m >= 0 && m < NN)
            s = fmaf(g_coef[j*NN + n], Wg[(size_t)d * NN + m], s);
    }
    g_Wp[(size_t)d * NN + n] = s;
}

// ---------------- tensor-core GEMM: C = act(A[M,K] @ W[N,K]^T + bias) ----------------
// tf32 m16n8k8 mma. Block tile (NWM*32) x 128, BK=32. NWM*2 warps, each warp 32x64.
// Smem layout [rows][36]: stride 36 words => fragment LDS banks are (4m + k) % 32 =
// laneid + const -> conflict-free.
template<int NWM, int ACT>
__global__ __launch_bounds__(NWM*64, 2)
void mma_gemm(const float* __restrict__ A,
              const float* __restrict__ W,
              const float* __restrict__ bias,
              float* __restrict__ C,
              int M, int N, int K)
{
    constexpr int THREADS = NWM * 64;
    constexpr int BM = NWM * 32;
    constexpr int WL = 16 / NWM;     // W-staging float4 loads per thread

    __shared__ unsigned As[BM][36];
    __shared__ unsigned Ws[128][36];

    const int tid  = threadIdx.x;
    const int wid  = tid >> 5;
    const int lane = tid & 31;
    const int gid  = lane >> 2;      // 0..7
    const int tig  = lane & 3;       // 0..3
    const int warp_m = wid % NWM;
    const int warp_n = wid / NWM;
    const int mBase = blockIdx.y * BM;
    const int nBase = blockIdx.x * 128;

    float acc[2][8][4];
#pragma unroll
    for (int mi = 0; mi < 2; mi++)
#pragma unroll
        for (int ni = 0; ni < 8; ni++)
#pragma unroll
            for (int j = 0; j < 4; j++) acc[mi][ni][j] = 0.0f;

    for (int k0 = 0; k0 < K; k0 += 32) {
        // stage A tile: BM x 32
#pragma unroll
        for (int i = 0; i < 4; i++) {
            int idx = tid + i * THREADS;
            int r = idx >> 3, c = (idx & 7) * 4;
            float4 v = *reinterpret_cast<const float4*>(A + (size_t)(mBase + r) * K + k0 + c);
            As[r][c+0] = f2tf(v.x); As[r][c+1] = f2tf(v.y);
            As[r][c+2] = f2tf(v.z); As[r][c+3] = f2tf(v.w);
        }
        // stage W tile: 128 x 32
#pragma unroll
        for (int i = 0; i < WL; i++) {
            int idx = tid + i * THREADS;
            int r = idx >> 3, c = (idx & 7) * 4;
            float4 v = *reinterpret_cast<const float4*>(W + (size_t)(nBase + r) * K + k0 + c);
            Ws[r][c+0] = f2tf(v.x); Ws[r][c+1] = f2tf(v.y);
            Ws[r][c+2] = f2tf(v.z); Ws[r][c+3] = f2tf(v.w);
        }
        __syncthreads();

#pragma unroll
        for (int ks = 0; ks < 4; ks++) {
            const int kk = ks * 8;
            unsigned af[2][4], bf[8][2];
#pragma unroll
            for (int mi = 0; mi < 2; mi++) {
                int mr = warp_m * 32 + mi * 16 + gid;
                af[mi][0] = As[mr    ][kk + tig];
                af[mi][1] = As[mr + 8][kk + tig];
                af[mi][2] = As[mr    ][kk + tig + 4];
                af[mi][3] = As[mr + 8][kk + tig + 4];
            }
#pragma unroll
            for (int ni = 0; ni < 8; ni++) {
                int nc = warp_n * 64 + ni * 8 + gid;
                bf[ni][0] = Ws[nc][kk + tig];
                bf[ni][1] = Ws[nc][kk + tig + 4];
            }
#pragma unroll
            for (int mi = 0; mi < 2; mi++)
#pragma unroll
                for (int ni = 0; ni < 8; ni++)
                    mma_tf32(acc[mi][ni], af[mi], bf[ni]);
        }
        __syncthreads();
    }

    // epilogue: c0=(gid, 2t), c1=(gid, 2t+1), c2=(gid+8, 2t), c3=(gid+8, 2t+1)
#pragma unroll
    for (int mi = 0; mi < 2; mi++) {
        int m0 = mBase + warp_m * 32 + mi * 16 + gid;
#pragma unroll
        for (int ni = 0; ni < 8; ni++) {
            int n0 = nBase + warp_n * 64 + ni * 8 + tig * 2;
            float b0 = bias[n0], b1 = bias[n0 + 1];
            float v0 = acc[mi][ni][0] + b0;
            float v1 = acc[mi][ni][1] + b1;
            float v2 = acc[mi][ni][2] + b0;
            float v3 = acc[mi][ni][3] + b1;
            if (ACT) { v0 = sigm(v0); v1 = sigm(v1); v2 = sigm(v2); v3 = sigm(v3); }
            float2 lo; lo.x = v0; lo.y = v1;
            float2 hi; hi.x = v2; hi.y = v3;
            *reinterpret_cast<float2*>(C + (size_t)m0 * N + n0)       = lo;
            *reinterpret_cast<float2*>(C + (size_t)(m0 + 8) * N + n0) = hi;
        }
    }
}

// ---------------- GRU pieces ----------------
__global__ void set_h(const float* __restrict__ src)
{
    int i = blockIdx.x * blockDim.x + threadIdx.x;
    g_h[i] = src[i];
}

__global__ void gru_gate(const float* __restrict__ xW,
                         const float* __restrict__ hW,
                         float* __restrict__ h,
                         float* __restrict__ hs_out)
{
    int idx = blockIdx.x * blockDim.x + threadIdx.x;
    int b = idx / HID, j = idx % HID;
    size_t base = (size_t)b * 3 * HID;
    float r = sigm(xW[base + j]          + hW[base + j]);
    float z = sigm(xW[base + HID + j]    + hW[base + HID + j]);
    float n = tanhf(xW[base + 2*HID + j] + r * hW[base + 2*HID + j]);
    float hp = h[idx];
    float hn = (1.0f - z) * n + z * hp;
    h[idx] = hn;
    if (hs_out) hs_out[idx] = hn;
}

// ---------------- final 3-layer sigmoid MLP ----------------
__global__ void final_mlp(const float* __restrict__ h,
                          const float* __restrict__ Wf0, const float* __restrict__ bf0,
                          const float* __restrict__ Wf1, const float* __restrict__ bf1,
                          const float* __restrict__ Wf2, const float* __restrict__ bf2,
                          float* __restrict__ out)
{
    __shared__ float sW0[16][257];
    __shared__ float sh [16][256];
    __shared__ float s1 [16][17];
    __shared__ float s2 [16][17];

    int tid = threadIdx.x;
    int bb  = blockIdx.x * 16;

    for (int i = tid; i < 16 * 256; i += 256) sW0[i / 256][i % 256] = Wf0[i];
    for (int i = tid; i < 16 * 256; i += 256) sh [i / 256][i % 256] = h[(size_t)bb * 256 + i];
    __syncthreads();

    int r = tid / 16, j = tid % 16;
    float a0 = bf0[j];
#pragma unroll 8
    for (int k = 0; k < 256; k++) a0 = fmaf(sh[r][k], sW0[j][k], a0);
    s1[r][j] = sigm(a0);
    __syncthreads();

    float a1 = bf1[j];
#pragma unroll
    for (int k = 0; k < 16; k++) a1 = fmaf(s1[r][k], Wf1[j * 16 + k], a1);
    s2[r][j] = sigm(a1);
    __syncthreads();

    if (j == 0) {
        float a2 = bf2[0];
#pragma unroll
        for (int k = 0; k < 16; k++) a2 = fmaf(s2[r][k], Wf2[k], a2);
        out[bb + r] = sigm(a2);
    }
}

// ---------------- launch ----------------
extern "C" void kernel_launch(void* const* d_in, const int* in_sizes, int n_in,
                              void* d_out, int out_size)
{
    const float* x     = (const float*)d_in[0];
    const float* h0    = (const float*)d_in[1];
    const float* Aadj  = (const float*)d_in[2];
    const float* W_gnn = (const float*)d_in[3];
    const float* b_gnn = (const float*)d_in[4];
    const float* W_lin = (const float*)d_in[5];
    const float* b_lin = (const float*)d_in[6];
    const float* Wih0  = (const float*)d_in[7];
    const float* Whh0  = (const float*)d_in[8];
    const float* bih0  = (const float*)d_in[9];
    const float* bhh0  = (const float*)d_in[10];
    const float* Wih1  = (const float*)d_in[11];
    const float* Whh1  = (const float*)d_in[12];
    const float* bih1  = (const float*)d_in[13];
    const float* bhh1  = (const float*)d_in[14];
    const float* Wf0   = (const float*)d_in[15];
    const float* bf0   = (const float*)d_in[16];
    const float* Wf1   = (const float*)d_in[17];
    const float* bf1   = (const float*)d_in[18];
    const float* Wf2   = (const float*)d_in[19];
    const float* bf2   = (const float*)d_in[20];
    float* out = (float*)d_out;

    float *p_Wp, *p_t2, *p_t4, *p_xW, *p_hW, *p_hs, *p_h;
    cudaGetSymbolAddress((void**)&p_Wp, g_Wp);
    cudaGetSymbolAddress((void**)&p_t2, g_t2);
    cudaGetSymbolAddress((void**)&p_t4, g_t4);
    cudaGetSymbolAddress((void**)&p_xW, g_xW);
    cudaGetSymbolAddress((void**)&p_hW, g_hW);
    cudaGetSymbolAddress((void**)&p_hs, g_hs);
    cudaGetSymbolAddress((void**)&p_h,  g_h);

    // 0) fold A into W_gnn
    extract_coef<<<NN / 256, 256>>>(Aadj);
    build_wp<<<dim3(NN / 256, DD), 256>>>(W_gnn);

    // 1) t2 = sigmoid(x @ W'^T + b_gnn)   [12288,4096] x [4096,256]  (tf32 mma)
    mma_gemm<4, 1><<<dim3(DD / 128, MALL / 128), 256>>>(x, p_Wp, b_gnn, p_t2, MALL, DD, NN);

    // 2) t4 = sigmoid(t2 @ W_lin^T + b_lin)   [12288,256] x [256,256]
    mma_gemm<4, 1><<<dim3(DD / 128, MALL / 128), 256>>>(p_t2, W_lin, b_lin, p_t4, MALL, DD, DD);

    // 3) GRU layer 0: input projection + sequential recurrence
    mma_gemm<4, 0><<<dim3(3 * HID / 128, MALL / 128), 256>>>(p_t4, Wih0, bih0, p_xW, MALL, 3 * HID, DD);
    set_h<<<BATCH * HID / 256, 256>>>(h0);
    for (int t = 0; t < TSTEPS; t++) {
        mma_gemm<2, 0><<<dim3(3 * HID / 128, BATCH / 64), 128>>>(p_h, Whh0, bhh0, p_hW, BATCH, 3 * HID, HID);
        gru_gate<<<BATCH * HID / 256, 256>>>(p_xW + (size_t)t * BATCH * 3 * HID, p_hW,
                                             p_h, p_hs + (size_t)t * BATCH * HID);
    }

    // 4) GRU layer 1
    mma_gemm<4, 0><<<dim3(3 * HID / 128, MALL / 128), 256>>>(p_hs, Wih1, bih1, p_xW, MALL, 3 * HID, HID);
    set_h<<<BATCH * HID / 256, 256>>>(h0 + BATCH * HID);
    for (int t = 0; t < TSTEPS; t++) {
        mma_gemm<2, 0><<<dim3(3 * HID / 128, BATCH / 64), 128>>>(p_h, Whh1, bhh1, p_hW, BATCH, 3 * HID, HID);
        gru_gate<<<BATCH * HID / 256, 256>>>(p_xW + (size_t)t * BATCH * 3 * HID, p_hW,
                                             p_h, nullptr);
    }

    // 5) final MLP -> out [1024]
    final_mlp<<<BATCH / 16, 256>>>(p_h, Wf0, bf0, Wf1, bf1, Wf2, bf2, out);
}